// round 12
// baseline (speedup 1.0000x reference)
#include <cuda_runtime.h>
#include <cuda_bf16.h>
#include <cstdint>
#include <cstddef>

#define BATCH   4096
#define INDIM   1024
#define DICT    16384
#define KHALF   32
#define MAXSEL  64
#define CANDMAX 160
#define MARGIN  0.06f

// ---------------- __device__ scratch (no allocs) ----------------------------
__device__ __nv_bfloat16 g_xb [2][(size_t)BATCH * INDIM];
__device__ __nv_bfloat16 g_Wtb[2][(size_t)DICT * INDIM];   // W^T bf16 [N,K]
__device__ float         g_Wt [2][(size_t)DICT * INDIM];   // W^T fp32 [N,K]
__device__ __nv_bfloat16 g_hb [2][(size_t)BATCH * DICT];   // h~ bf16
__device__ int   g_cn [2][BATCH];
__device__ int   g_ci [2][BATCH][CANDMAX];
__device__ int   g_nsel[BATCH];
__device__ int   g_idx [BATCH * MAXSEL];
__device__ float g_hu  [BATCH * MAXSEL];
__device__ float g_hc  [BATCH * MAXSEL];

// ---------------- PTX helpers (sm_80-era only) -------------------------------
__device__ __forceinline__ uint32_t smem_u32(const void* p) {
    uint32_t a;
    asm("{ .reg .u64 t; cvta.to.shared.u64 t, %1; cvt.u32.u64 %0, t; }" : "=r"(a) : "l"(p));
    return a;
}
__device__ __forceinline__ void cpa16(uint32_t s, const void* g) {
    asm volatile("cp.async.cg.shared.global [%0], [%1], 16;" :: "r"(s), "l"(g));
}
__device__ __forceinline__ void cpa_commit() { asm volatile("cp.async.commit_group;" ::: "memory"); }
__device__ __forceinline__ void cpa_wait1()  { asm volatile("cp.async.wait_group 1;" ::: "memory"); }

__device__ __forceinline__ void ldsm4(uint32_t* r, uint32_t addr) {
    asm volatile("ldmatrix.sync.aligned.m8n8.x4.shared.b16 {%0,%1,%2,%3}, [%4];"
        : "=r"(r[0]), "=r"(r[1]), "=r"(r[2]), "=r"(r[3]) : "r"(addr));
}
__device__ __forceinline__ void mma16816(float* d, const uint32_t* a, const uint32_t* b) {
    asm volatile("mma.sync.aligned.m16n8k16.row.col.f32.bf16.bf16.f32 "
        "{%0,%1,%2,%3}, {%4,%5,%6,%7}, {%8,%9}, {%0,%1,%2,%3};"
        : "+f"(d[0]), "+f"(d[1]), "+f"(d[2]), "+f"(d[3])
        : "r"(a[0]), "r"(a[1]), "r"(a[2]), "r"(a[3]), "r"(b[0]), "r"(b[1]));
}

// ---------------- preprocessing ---------------------------------------------
__global__ void conv_x(const float* __restrict__ xu, const float* __restrict__ xc)
{
    size_t n = (size_t)BATCH * INDIM;
    for (size_t i = (size_t)blockIdx.x * blockDim.x + threadIdx.x; i < n;
         i += (size_t)gridDim.x * blockDim.x) {
        g_xb[0][i] = __float2bfloat16_rn(xu[i]);
        g_xb[1][i] = __float2bfloat16_rn(xc[i]);
    }
}

__global__ void trans_w(const float* __restrict__ Wu, const float* __restrict__ Wc)
{
    __shared__ float t[32][33];
    const int enc = blockIdx.z;
    const float* W = enc ? Wc : Wu;
    const int n0 = blockIdx.x * 32, k0 = blockIdx.y * 32;
    const int tx = threadIdx.x, ty = threadIdx.y;
    #pragma unroll
    for (int j = 0; j < 4; j++)
        t[ty + j * 8][tx] = W[(size_t)(k0 + ty + j * 8) * DICT + n0 + tx];
    __syncthreads();
    #pragma unroll
    for (int j = 0; j < 4; j++) {
        float v = t[tx][ty + j * 8];
        size_t o = (size_t)(n0 + ty + j * 8) * INDIM + k0 + tx;
        g_Wt [enc][o] = v;
        g_Wtb[enc][o] = __float2bfloat16_rn(v);
    }
}

// -- bf16 mma.sync GEMM: CTA 128x128x64, 4 warps, warp 64x64, 2 stages --------
#define GBM 128
#define GBN 128
#define GBK 64
#define GROWB 72                 // 64 bf16 + 8 pad = 144 B rows
#define ASTG  18432              // 128 * 144
#define GSTB  (2 * ASTG)         // 36864
#define GST   2
#define GEMM_SMEM (GST * GSTB)   // 73728
#define NKI (INDIM / GBK)        // 16
#define GTHREADS 128

__device__ __forceinline__ void g_load(uint32_t sbase,
    const __nv_bfloat16* __restrict__ Xb, const __nv_bfloat16* __restrict__ Wb,
    int m0, int n0, int k0, int tid)
{
    #pragma unroll
    for (int r = 0; r < 8; r++) {
        int i = tid + r * GTHREADS;          // 0..1023
        int row = i >> 3, c = i & 7;
        cpa16(sbase + row * 144 + c * 16,
              Xb + (size_t)(m0 + row) * INDIM + k0 + c * 8);
        cpa16(sbase + ASTG + row * 144 + c * 16,
              Wb + (size_t)(n0 + row) * INDIM + k0 + c * 8);
    }
}

__global__ void __launch_bounds__(GTHREADS, 2)
gemm_bf16(int enc, const float* __restrict__ bias,
          float* __restrict__ zfill, float* __restrict__ mfill)
{
    extern __shared__ __align__(128) char sm[];
    __shared__ float s_bias[GBN];
    const uint32_t sb = smem_u32(sm);
    const int tid = threadIdx.x, lane = tid & 31, wid = tid >> 5;
    const int wm = wid & 1, wn = wid >> 1;   // 2 x 2 warps, warp tile 64x64
    const int m0 = blockIdx.x * GBM;
    const int n0 = blockIdx.y * GBN;

    const __nv_bfloat16* Xb = g_xb [enc];
    const __nv_bfloat16* Wb = g_Wtb[enc];
    __nv_bfloat16* C = g_hb[enc];

    s_bias[tid] = bias[n0 + tid];

    const uint32_t aBase = ((wm * 64 + (lane & 15)) * GROWB + ((lane >> 4) << 3)) * 2;
    const uint32_t bBase = ((wn * 64 + (lane & 7) + ((lane >> 4) << 3)) * GROWB
                           + (((lane >> 3) & 1) << 3)) * 2;

    #pragma unroll
    for (int p = 0; p < GST; p++) {
        g_load(sb + p * GSTB, Xb, Wb, m0, n0, p * GBK, tid);
        cpa_commit();
    }

    float acc[4][8][4];
    #pragma unroll
    for (int a = 0; a < 4; a++)
        #pragma unroll
        for (int b = 0; b < 8; b++)
            #pragma unroll
            for (int c = 0; c < 4; c++) acc[a][b][c] = 0.f;

    for (int t = 0; t < NKI; t++) {
        const int s = t & 1;
        const uint32_t sA = sb + s * GSTB, sB = sA + ASTG;

        cpa_wait1();
        __syncthreads();

        #pragma unroll
        for (int ks = 0; ks < GBK; ks += 16) {
            uint32_t af[4][4];
            #pragma unroll
            for (int mi = 0; mi < 4; mi++)
                ldsm4(af[mi], sA + aBase + (mi * 16 * GROWB + ks) * 2);
            #pragma unroll
            for (int nh = 0; nh < 4; nh++) {
                uint32_t r[4];
                ldsm4(r, sB + bBase + (nh * 16 * GROWB + ks) * 2);
                #pragma unroll
                for (int mi = 0; mi < 4; mi++) {
                    mma16816(acc[mi][nh * 2],     af[mi], r);
                    mma16816(acc[mi][nh * 2 + 1], af[mi], r + 2);
                }
            }
        }
        __syncthreads();

        if (t + GST < NKI)
            g_load(sb + s * GSTB, Xb, Wb, m0, n0, (t + GST) * GBK, tid);
        cpa_commit();
    }

    #pragma unroll
    for (int mi = 0; mi < 4; mi++) {
        const int rbase = m0 + wm * 64 + mi * 16 + (lane >> 2);
        #pragma unroll
        for (int ni = 0; ni < 8; ni++) {
            const int cl = wn * 64 + ni * 8 + (lane & 3) * 2;
            const float b0 = s_bias[cl], b1 = s_bias[cl + 1];
            __nv_bfloat162 v0 = __float22bfloat162_rn(
                make_float2(acc[mi][ni][0] + b0, acc[mi][ni][1] + b1));
            __nv_bfloat162 v1 = __float22bfloat162_rn(
                make_float2(acc[mi][ni][2] + b0, acc[mi][ni][3] + b1));
            *reinterpret_cast<__nv_bfloat162*>(C + (size_t)rbase * DICT + n0 + cl) = v0;
            *reinterpret_cast<__nv_bfloat162*>(C + (size_t)(rbase + 8) * DICT + n0 + cl) = v1;
        }
    }

    // overlapped zero-fill of this CTA's output tiles (z region; mask for enc0)
    const float4 zz = make_float4(0.f, 0.f, 0.f, 0.f);
    #pragma unroll
    for (int i = tid; i < (GBM * GBN) / 4; i += GTHREADS) {
        const int r = i >> 5, c = i & 31;
        *reinterpret_cast<float4*>(zfill + (size_t)(m0 + r) * DICT + n0 + c * 4) = zz;
    }
    if (mfill) {
        #pragma unroll
        for (int i = tid; i < (GBM * GBN) / 4; i += GTHREADS) {
            const int r = i >> 5, c = i & 31;
            *reinterpret_cast<float4*>(mfill + (size_t)(m0 + r) * DICT + n0 + c * 4) = zz;
        }
    }
}

// ---------------- candidate selection (register-resident) --------------------
__global__ void __launch_bounds__(256)
topcand()
{
    __shared__ int wcnt[8];
    __shared__ int s_cnt;
    const int row = blockIdx.x, tid = threadIdx.x;
    const int lane = tid & 31, wid = tid >> 5;

    for (int stream = 0; stream < 2; stream++) {
        const __nv_bfloat16* src = g_hb[stream] + (size_t)row * DICT;
        uint4 d[8];
        #pragma unroll
        for (int j = 0; j < 8; j++)
            d[j] = reinterpret_cast<const uint4*>(src)[tid + j * 256];

        unsigned lo = 0, hi = 0xFFFFu;
        #pragma unroll 1
        while (lo < hi) {
            const unsigned mid = (lo + hi + 1) >> 1;
            const unsigned short tb = (mid & 0x8000u)
                ? (unsigned short)(mid & 0x7FFFu)
                : (unsigned short)(~mid & 0xFFFFu);
            __nv_bfloat16_raw rr; rr.x = tb;
            const __nv_bfloat16 t1 = __nv_bfloat16(rr);
            const __nv_bfloat162 tv = __nv_bfloat162(t1, t1);

            __nv_bfloat162 accp = __nv_bfloat162(__float2bfloat16(0.f), __float2bfloat16(0.f));
            #pragma unroll
            for (int j = 0; j < 8; j++) {
                const __nv_bfloat162* p = reinterpret_cast<const __nv_bfloat162*>(&d[j]);
                #pragma unroll
                for (int q = 0; q < 4; q++)
                    accp = __hadd2(accp, __hge2(p[q], tv));
            }
            int c = (int)(__low2float(accp) + __high2float(accp));
            #pragma unroll
            for (int o = 16; o > 0; o >>= 1)
                c += __shfl_down_sync(0xFFFFFFFFu, c, o);
            if (lane == 0) wcnt[wid] = c;
            __syncthreads();
            if (tid == 0) {
                int tot = 0;
                #pragma unroll
                for (int w = 0; w < 8; w++) tot += wcnt[w];
                s_cnt = tot;
            }
            __syncthreads();
            if (s_cnt >= KHALF) lo = mid; else hi = mid - 1;
            __syncthreads();
        }

        const unsigned short vb = (lo & 0x8000u)
            ? (unsigned short)(lo & 0x7FFFu)
            : (unsigned short)(~lo & 0xFFFFu);
        __nv_bfloat16_raw vr; vr.x = vb;
        const float cut = __bfloat162float(__nv_bfloat16(vr)) - MARGIN;

        if (tid == 0) s_cnt = 0;
        __syncthreads();
        #pragma unroll
        for (int j = 0; j < 8; j++) {
            const __nv_bfloat16* p = reinterpret_cast<const __nv_bfloat16*>(&d[j]);
            #pragma unroll
            for (int q = 0; q < 8; q++) {
                if (__bfloat162float(p[q]) > cut) {
                    int pos = atomicAdd(&s_cnt, 1);
                    if (pos < CANDMAX)
                        g_ci[stream][row][pos] = (tid + j * 256) * 8 + q;
                }
            }
        }
        __syncthreads();
        if (tid == 0) g_cn[stream][row] = s_cnt < CANDMAX ? s_cnt : CANDMAX;
        __syncthreads();
    }
}

// ---------------- exact rescore + selection + scatter ------------------------
__global__ void __launch_bounds__(256)
rescore(const float* __restrict__ xu, const float* __restrict__ xc,
        const float* __restrict__ bu, const float* __restrict__ bc,
        float* __restrict__ zu, float* __restrict__ zc, float* __restrict__ mk)
{
    __shared__ float sxu[INDIM], sxc[INDIM];
    __shared__ int   ci[2][CANDMAX];
    __shared__ float chu[2][CANDMAX], chc[2][CANDMAX];
    __shared__ int   nc[2];
    __shared__ int   selidx[2][KHALF];
    __shared__ float selhu[2][KHALF], selhc[2][KHALF];
    __shared__ int   cnt;

    const int row = blockIdx.x, tid = threadIdx.x;
    const int lane = tid & 31, wid = tid >> 5;

    for (int i = tid; i < INDIM; i += 256) {
        sxu[i] = xu[(size_t)row * INDIM + i];
        sxc[i] = xc[(size_t)row * INDIM + i];
    }
    if (tid < 2) nc[tid] = g_cn[tid][row];
    __syncthreads();
    for (int s = 0; s < 2; s++)
        for (int t = tid; t < nc[s]; t += 256) ci[s][t] = g_ci[s][row][t];
    __syncthreads();

    const int tot = nc[0] + nc[1];
    for (int t = wid; t < tot; t += 8) {
        const int s  = (t < nc[0]) ? 0 : 1;
        const int tt = (s == 0) ? t : t - nc[0];
        const int j  = ci[s][tt];
        const float* wu = g_Wt[0] + (size_t)j * INDIM;
        const float* wc = g_Wt[1] + (size_t)j * INDIM;
        float su = 0.f, sc2 = 0.f;
        for (int i = lane; i < INDIM; i += 32) {
            su  += sxu[i] * __ldg(wu + i);
            sc2 += sxc[i] * __ldg(wc + i);
        }
        #pragma unroll
        for (int o = 16; o > 0; o >>= 1) {
            su  += __shfl_down_sync(0xFFFFFFFFu, su,  o);
            sc2 += __shfl_down_sync(0xFFFFFFFFu, sc2, o);
        }
        if (lane == 0) {
            chu[s][tt] = su  + bu[j];
            chc[s][tt] = sc2 + bc[j];
        }
    }
    __syncthreads();

    #pragma unroll
    for (int s = 0; s < 2; s++) {
        if (tid < nc[s]) {
            const float v = s ? chc[1][tid] : chu[0][tid];
            const int   j = ci[s][tid];
            int r = 0;
            for (int t2 = 0; t2 < nc[s]; t2++) {
                const float o = s ? chc[1][t2] : chu[0][t2];
                r += (o > v) || (o == v && ci[s][t2] < j);
            }
            if (r < KHALF) {
                selidx[s][r] = j;
                selhu[s][r]  = chu[s][tid];
                selhc[s][r]  = chc[s][tid];
            }
        }
    }
    __syncthreads();
    if (tid == 0) cnt = KHALF;
    __syncthreads();

    if (tid < KHALF) {
        g_idx[row * MAXSEL + tid] = selidx[0][tid];
        g_hu [row * MAXSEL + tid] = selhu[0][tid];
        g_hc [row * MAXSEL + tid] = selhc[0][tid];
    }
    if (tid < KHALF) {
        const int j = selidx[1][tid];
        bool dup = false;
        #pragma unroll
        for (int q = 0; q < KHALF; q++) dup |= (selidx[0][q] == j);
        if (!dup) {
            int p = atomicAdd(&cnt, 1);
            g_idx[row * MAXSEL + p] = j;
            g_hu [row * MAXSEL + p] = selhu[1][tid];
            g_hc [row * MAXSEL + p] = selhc[1][tid];
        }
    }
    __syncthreads();
    if (tid == 0) g_nsel[row] = cnt;
    __syncthreads();

    if (tid < g_nsel[row]) {
        const int idx = g_idx[row * MAXSEL + tid];
        const size_t o = (size_t)row * DICT + idx;
        mk[o] = 1.0f;
        zu[o] = fmaxf(g_hu[row * MAXSEL + tid], 0.f);
        zc[o] = fmaxf(g_hc[row * MAXSEL + tid], 0.f);
    }
}

// ---------------- decode (both decoders in one launch) ------------------------
__global__ void __launch_bounds__(256)
decode_kernel(const float* __restrict__ Wdu, const float* __restrict__ Wdc,
              float* __restrict__ xuh, float* __restrict__ xuc,
              float* __restrict__ xch, float* __restrict__ xcc)
{
    __shared__ int   sn;
    __shared__ int   sidx[MAXSEL];
    __shared__ float ca[MAXSEL], cb[MAXSEL];
    const int row    = blockIdx.x & (BATCH - 1);
    const int A_is_u = (blockIdx.x < BATCH);
    const int tid = threadIdx.x;

    const float* Wd   = A_is_u ? Wdu : Wdc;
    float* outA       = A_is_u ? xuh : xch;
    float* outB       = A_is_u ? xuc : xcc;

    if (tid == 0) sn = g_nsel[row];
    if (tid < MAXSEL) {
        sidx[tid] = g_idx[row * MAXSEL + tid];
        float zu = fmaxf(g_hu[row * MAXSEL + tid], 0.f);
        float zc = fmaxf(g_hc[row * MAXSEL + tid], 0.f);
        ca[tid] = A_is_u ? zu : zc;
        cb[tid] = A_is_u ? zc : zu;
    }
    __syncthreads();

    float4 a = make_float4(0.f, 0.f, 0.f, 0.f);
    float4 b = make_float4(0.f, 0.f, 0.f, 0.f);
    const int n = sn;
    #pragma unroll 4
    for (int s = 0; s < n; s++) {
        const float4 w = *reinterpret_cast<const float4*>(
            Wd + (size_t)sidx[s] * INDIM + tid * 4);
        const float fa = ca[s], fb = cb[s];
        a.x += fa * w.x; a.y += fa * w.y; a.z += fa * w.z; a.w += fa * w.w;
        b.x += fb * w.x; b.y += fb * w.y; b.z += fb * w.z; b.w += fb * w.w;
    }
    const size_t o = (size_t)row * INDIM + tid * 4;
    *reinterpret_cast<float4*>(outA + o) = a;
    *reinterpret_cast<float4*>(outB + o) = b;
}

// ---------------- launch ----------------------------------------------------
extern "C" void kernel_launch(void* const* d_in, const int* in_sizes, int n_in,
                              void* d_out, int out_size)
{
    const float* x_u     = (const float*)d_in[0];
    const float* x_c     = (const float*)d_in[1];
    const float* W_enc_u = (const float*)d_in[2];
    const float* b_enc_u = (const float*)d_in[3];
    const float* W_enc_c = (const float*)d_in[4];
    const float* b_enc_c = (const float*)d_in[5];
    const float* W_dec_u = (const float*)d_in[6];
    const float* W_dec_c = (const float*)d_in[7];

    float* out = (float*)d_out;
    const size_t ZN = (size_t)BATCH * DICT;
    const size_t XN = (size_t)BATCH * INDIM;
    float* z_u = out;
    float* z_c = out + ZN;
    float* mk  = out + 2 * ZN;
    float* xuh = out + 3 * ZN;
    float* xch = xuh + XN;
    float* xuc = xch + XN;
    float* xcc = xuc + XN;

    cudaFuncSetAttribute(gemm_bf16, cudaFuncAttributeMaxDynamicSharedMemorySize, GEMM_SMEM);

    conv_x<<<2048, 256>>>(x_u, x_c);
    trans_w<<<dim3(DICT / 32, INDIM / 32, 2), dim3(32, 8)>>>(W_enc_u, W_enc_c);

    dim3 ggrid(BATCH / GBM, DICT / GBN);   // (32, 128)
    gemm_bf16<<<ggrid, GTHREADS, GEMM_SMEM>>>(0, b_enc_u, z_u, mk);
    gemm_bf16<<<ggrid, GTHREADS, GEMM_SMEM>>>(1, b_enc_c, z_c, nullptr);

    topcand<<<BATCH, 256>>>();

    rescore<<<BATCH, 256>>>(x_u, x_c, b_enc_u, b_enc_c, z_u, z_c, mk);

    decode_kernel<<<2 * BATCH, 256>>>(W_dec_u, W_dec_c, xuh, xuc, xch, xcc);
}

// round 13
// speedup vs baseline: 1.0043x; 1.0043x over previous
#include <cuda_runtime.h>
#include <cuda_bf16.h>
#include <cstdint>
#include <cstddef>

#define BATCH   4096
#define INDIM   1024
#define DICT    16384
#define KHALF   32
#define MAXSEL  64
#define CANDMAX 160
#define MARGIN  0.06f

// ---------------- __device__ scratch (no allocs) ----------------------------
__device__ __nv_bfloat16 g_xb [2][(size_t)BATCH * INDIM];
__device__ __nv_bfloat16 g_Wtb[2][(size_t)DICT * INDIM];   // W^T bf16 [N,K]
__device__ float         g_Wt [2][(size_t)DICT * INDIM];   // W^T fp32 [N,K]
__device__ __nv_bfloat16 g_hb [2][(size_t)BATCH * DICT];   // h~ bf16
__device__ int   g_cn [2][BATCH];
__device__ int   g_ci [2][BATCH][CANDMAX];
__device__ int   g_nsel[BATCH];
__device__ int   g_idx [BATCH * MAXSEL];
__device__ float g_hu  [BATCH * MAXSEL];
__device__ float g_hc  [BATCH * MAXSEL];

// ---------------- PTX helpers (sm_80-era only) -------------------------------
__device__ __forceinline__ uint32_t smem_u32(const void* p) {
    uint32_t a;
    asm("{ .reg .u64 t; cvta.to.shared.u64 t, %1; cvt.u32.u64 %0, t; }" : "=r"(a) : "l"(p));
    return a;
}
__device__ __forceinline__ void cpa16(uint32_t s, const void* g) {
    asm volatile("cp.async.cg.shared.global [%0], [%1], 16;" :: "r"(s), "l"(g));
}
__device__ __forceinline__ void cpa_commit() { asm volatile("cp.async.commit_group;" ::: "memory"); }
__device__ __forceinline__ void cpa_wait3()  { asm volatile("cp.async.wait_group 3;" ::: "memory"); }

__device__ __forceinline__ void ldsm4(uint32_t* r, uint32_t addr) {
    asm volatile("ldmatrix.sync.aligned.m8n8.x4.shared.b16 {%0,%1,%2,%3}, [%4];"
        : "=r"(r[0]), "=r"(r[1]), "=r"(r[2]), "=r"(r[3]) : "r"(addr));
}
__device__ __forceinline__ void mma16816(float* d, const uint32_t* a, const uint32_t* b) {
    asm volatile("mma.sync.aligned.m16n8k16.row.col.f32.bf16.bf16.f32 "
        "{%0,%1,%2,%3}, {%4,%5,%6,%7}, {%8,%9}, {%0,%1,%2,%3};"
        : "+f"(d[0]), "+f"(d[1]), "+f"(d[2]), "+f"(d[3])
        : "r"(a[0]), "r"(a[1]), "r"(a[2]), "r"(a[3]), "r"(b[0]), "r"(b[1]));
}

// ---------------- preprocessing ---------------------------------------------
__global__ void conv_x(const float* __restrict__ xu, const float* __restrict__ xc)
{
    size_t n = (size_t)BATCH * INDIM;
    for (size_t i = (size_t)blockIdx.x * blockDim.x + threadIdx.x; i < n;
         i += (size_t)gridDim.x * blockDim.x) {
        g_xb[0][i] = __float2bfloat16_rn(xu[i]);
        g_xb[1][i] = __float2bfloat16_rn(xc[i]);
    }
}

__global__ void trans_w(const float* __restrict__ Wu, const float* __restrict__ Wc)
{
    __shared__ float t[32][33];
    const int enc = blockIdx.z;
    const float* W = enc ? Wc : Wu;
    const int n0 = blockIdx.x * 32, k0 = blockIdx.y * 32;
    const int tx = threadIdx.x, ty = threadIdx.y;
    #pragma unroll
    for (int j = 0; j < 4; j++)
        t[ty + j * 8][tx] = W[(size_t)(k0 + ty + j * 8) * DICT + n0 + tx];
    __syncthreads();
    #pragma unroll
    for (int j = 0; j < 4; j++) {
        float v = t[tx][ty + j * 8];
        size_t o = (size_t)(n0 + ty + j * 8) * INDIM + k0 + tx;
        g_Wt [enc][o] = v;
        g_Wtb[enc][o] = __float2bfloat16_rn(v);
    }
}

// -- bf16 mma.sync GEMM (R11 config): CTA 128x128x32, 4 warps, warp 64x64,
//    4 stages, reg double-buffered frags, both encoders in one launch (grid.z)
#define GBM 128
#define GBN 128
#define GBK 32
#define GROWB 40
#define GSTB  20480
#define GST   4
#define GEMM_SMEM (GST * GSTB)   // 81920
#define NKI (INDIM / GBK)
#define GTHREADS 128

__device__ __forceinline__ void g_load(uint32_t sbase,
    const __nv_bfloat16* __restrict__ Xb, const __nv_bfloat16* __restrict__ Wb,
    int m0, int n0, int k0, int tid)
{
    #pragma unroll
    for (int r = 0; r < 4; r++) {
        int i = tid + r * GTHREADS;
        int row = i >> 2, c = i & 3;
        cpa16(sbase + row * 80 + c * 16,
              Xb + (size_t)(m0 + row) * INDIM + k0 + c * 8);
        cpa16(sbase + 10240 + row * 80 + c * 16,
              Wb + (size_t)(n0 + row) * INDIM + k0 + c * 8);
    }
}

__global__ void __launch_bounds__(GTHREADS, 2)
gemm_bf16(const float* __restrict__ bu, const float* __restrict__ bc,
          float* __restrict__ z_u, float* __restrict__ z_c, float* __restrict__ mk)
{
    extern __shared__ __align__(128) char sm[];
    __shared__ float s_bias[GBN];
    const uint32_t sb = smem_u32(sm);
    const int tid = threadIdx.x, lane = tid & 31, wid = tid >> 5;
    const int wm = wid & 1, wn = wid >> 1;
    const int enc = blockIdx.z;
    const int m0 = blockIdx.x * GBM;
    const int n0 = blockIdx.y * GBN;

    const float* bias = enc ? bc : bu;
    float* zfill = enc ? z_c : z_u;
    float* mfill = enc ? nullptr : mk;

    const __nv_bfloat16* Xb = g_xb [enc];
    const __nv_bfloat16* Wb = g_Wtb[enc];
    __nv_bfloat16* C = g_hb[enc];

    s_bias[tid] = bias[n0 + tid];

    const uint32_t aBase = ((wm * 64 + (lane & 15)) * GROWB + ((lane >> 4) << 3)) * 2;
    const uint32_t bBase = ((wn * 64 + (lane & 7) + ((lane >> 4) << 3)) * GROWB
                           + (((lane >> 3) & 1) << 3)) * 2;

    #pragma unroll
    for (int p = 0; p < GST; p++) {
        g_load(sb + p * GSTB, Xb, Wb, m0, n0, p * GBK, tid);
        cpa_commit();
    }

    float acc[4][8][4];
    #pragma unroll
    for (int a = 0; a < 4; a++)
        #pragma unroll
        for (int b = 0; b < 8; b++)
            #pragma unroll
            for (int c = 0; c < 4; c++) acc[a][b][c] = 0.f;

    for (int t = 0; t < NKI; t++) {
        const int s = t & (GST - 1);
        const uint32_t sA = sb + s * GSTB, sB = sA + 10240;

        cpa_wait3();
        __syncthreads();

        uint32_t af[2][4][4];
        uint32_t bf[2][4];

        #pragma unroll
        for (int mi = 0; mi < 4; mi++)
            ldsm4(af[0][mi], sA + aBase + (mi * 16 * GROWB) * 2);
        ldsm4(bf[0], sB + bBase);

        #pragma unroll
        for (int ks2 = 0; ks2 < 2; ks2++) {
            #pragma unroll
            for (int nh = 0; nh < 4; nh++) {
                const int cur = (ks2 * 4 + nh) & 1, nxt = cur ^ 1;
                if (nh < 3)
                    ldsm4(bf[nxt], sB + bBase + (ks2 * 16 + (nh + 1) * 16 * GROWB) * 2);
                else if (ks2 == 0)
                    ldsm4(bf[nxt], sB + bBase + 16 * 2);
                if (ks2 == 0 && nh == 2) {
                    ldsm4(af[1][0], sA + aBase + (16 + 0 * 16 * GROWB) * 2);
                    ldsm4(af[1][1], sA + aBase + (16 + 1 * 16 * GROWB) * 2);
                }
                if (ks2 == 0 && nh == 3) {
                    ldsm4(af[1][2], sA + aBase + (16 + 2 * 16 * GROWB) * 2);
                    ldsm4(af[1][3], sA + aBase + (16 + 3 * 16 * GROWB) * 2);
                }
                #pragma unroll
                for (int mi = 0; mi < 4; mi++) {
                    mma16816(acc[mi][nh * 2],     af[ks2][mi], bf[cur]);
                    mma16816(acc[mi][nh * 2 + 1], af[ks2][mi], bf[cur] + 2);
                }
            }
        }
        __syncthreads();

        if (t + GST < NKI)
            g_load(sb + s * GSTB, Xb, Wb, m0, n0, (t + GST) * GBK, tid);
        cpa_commit();
    }

    #pragma unroll
    for (int mi = 0; mi < 4; mi++) {
        const int rbase = m0 + wm * 64 + mi * 16 + (lane >> 2);
        #pragma unroll
        for (int ni = 0; ni < 8; ni++) {
            const int cl = wn * 64 + ni * 8 + (lane & 3) * 2;
            const float b0 = s_bias[cl], b1 = s_bias[cl + 1];
            __nv_bfloat162 v0 = __float22bfloat162_rn(
                make_float2(acc[mi][ni][0] + b0, acc[mi][ni][1] + b1));
            __nv_bfloat162 v1 = __float22bfloat162_rn(
                make_float2(acc[mi][ni][2] + b0, acc[mi][ni][3] + b1));
            *reinterpret_cast<__nv_bfloat162*>(C + (size_t)rbase * DICT + n0 + cl) = v0;
            *reinterpret_cast<__nv_bfloat162*>(C + (size_t)(rbase + 8) * DICT + n0 + cl) = v1;
        }
    }

    const float4 zz = make_float4(0.f, 0.f, 0.f, 0.f);
    #pragma unroll
    for (int i = tid; i < (GBM * GBN) / 4; i += GTHREADS) {
        const int r = i >> 5, c = i & 31;
        *reinterpret_cast<float4*>(zfill + (size_t)(m0 + r) * DICT + n0 + c * 4) = zz;
    }
    if (mfill) {
        #pragma unroll
        for (int i = tid; i < (GBM * GBN) / 4; i += GTHREADS) {
            const int r = i >> 5, c = i & 31;
            *reinterpret_cast<float4*>(mfill + (size_t)(m0 + r) * DICT + n0 + c * 4) = zz;
        }
    }
}

// ---------------- candidate selection (register-resident) --------------------
__global__ void __launch_bounds__(256)
topcand()
{
    __shared__ int wcnt[8];
    __shared__ int s_cnt;
    const int row = blockIdx.x, tid = threadIdx.x;
    const int lane = tid & 31, wid = tid >> 5;

    for (int stream = 0; stream < 2; stream++) {
        const __nv_bfloat16* src = g_hb[stream] + (size_t)row * DICT;
        uint4 d[8];
        #pragma unroll
        for (int j = 0; j < 8; j++)
            d[j] = reinterpret_cast<const uint4*>(src)[tid + j * 256];

        unsigned lo = 0, hi = 0xFFFFu;
        #pragma unroll 1
        while (lo < hi) {
            const unsigned mid = (lo + hi + 1) >> 1;
            const unsigned short tb = (mid & 0x8000u)
                ? (unsigned short)(mid & 0x7FFFu)
                : (unsigned short)(~mid & 0xFFFFu);
            __nv_bfloat16_raw rr; rr.x = tb;
            const __nv_bfloat16 t1 = __nv_bfloat16(rr);
            const __nv_bfloat162 tv = __nv_bfloat162(t1, t1);

            __nv_bfloat162 accp = __nv_bfloat162(__float2bfloat16(0.f), __float2bfloat16(0.f));
            #pragma unroll
            for (int j = 0; j < 8; j++) {
                const __nv_bfloat162* p = reinterpret_cast<const __nv_bfloat162*>(&d[j]);
                #pragma unroll
                for (int q = 0; q < 4; q++)
                    accp = __hadd2(accp, __hge2(p[q], tv));
            }
            int c = (int)(__low2float(accp) + __high2float(accp));
            #pragma unroll
            for (int o = 16; o > 0; o >>= 1)
                c += __shfl_down_sync(0xFFFFFFFFu, c, o);
            if (lane == 0) wcnt[wid] = c;
            __syncthreads();
            if (tid == 0) {
                int tot = 0;
                #pragma unroll
                for (int w = 0; w < 8; w++) tot += wcnt[w];
                s_cnt = tot;
            }
            __syncthreads();
            if (s_cnt >= KHALF) lo = mid; else hi = mid - 1;
            __syncthreads();
        }

        const unsigned short vb = (lo & 0x8000u)
            ? (unsigned short)(lo & 0x7FFFu)
            : (unsigned short)(~lo & 0xFFFFu);
        __nv_bfloat16_raw vr; vr.x = vb;
        const float cut = __bfloat162float(__nv_bfloat16(vr)) - MARGIN;

        if (tid == 0) s_cnt = 0;
        __syncthreads();
        #pragma unroll
        for (int j = 0; j < 8; j++) {
            const __nv_bfloat16* p = reinterpret_cast<const __nv_bfloat16*>(&d[j]);
            #pragma unroll
            for (int q = 0; q < 8; q++) {
                if (__bfloat162float(p[q]) > cut) {
                    int pos = atomicAdd(&s_cnt, 1);
                    if (pos < CANDMAX)
                        g_ci[stream][row][pos] = (tid + j * 256) * 8 + q;
                }
            }
        }
        __syncthreads();
        if (tid == 0) g_cn[stream][row] = s_cnt < CANDMAX ? s_cnt : CANDMAX;
        __syncthreads();
    }
}

// -------- exact rescore (two-phase) + selection + scatter ---------------------
__global__ void __launch_bounds__(256)
rescore(const float* __restrict__ xu, const float* __restrict__ xc,
        const float* __restrict__ bu, const float* __restrict__ bc,
        float* __restrict__ zu, float* __restrict__ zc, float* __restrict__ mk)
{
    __shared__ float sxu[INDIM], sxc[INDIM];
    __shared__ int   ci[2][CANDMAX];
    __shared__ float chown[2][CANDMAX];
    __shared__ int   nc[2];
    __shared__ int   selidx[2][KHALF];
    __shared__ float selval[2][KHALF];
    __shared__ int   fidx[MAXSEL];
    __shared__ float fhu[MAXSEL], fhc[MAXSEL];
    __shared__ int   fmiss[MAXSEL];   // 0: need hc, 1: need hu, 2: complete
    __shared__ int   cnt;

    const int row = blockIdx.x, tid = threadIdx.x;
    const int lane = tid & 31, wid = tid >> 5;

    for (int i = tid; i < INDIM; i += 256) {
        sxu[i] = xu[(size_t)row * INDIM + i];
        sxc[i] = xc[(size_t)row * INDIM + i];
    }
    if (tid < 2) nc[tid] = g_cn[tid][row];
    __syncthreads();
    for (int s = 0; s < 2; s++)
        for (int t = tid; t < nc[s]; t += 256) ci[s][t] = g_ci[s][row][t];
    __syncthreads();

    // ---- phase A: own-stream exact dots only (for ranking) ----
    const int tot = nc[0] + nc[1];
    for (int t = wid; t < tot; t += 8) {
        const int s  = (t < nc[0]) ? 0 : 1;
        const int tt = (s == 0) ? t : t - nc[0];
        const int j  = ci[s][tt];
        const float* w  = g_Wt[s] + (size_t)j * INDIM;
        const float* xx = s ? sxc : sxu;
        float acc = 0.f;
        for (int i = lane; i < INDIM; i += 32)
            acc += xx[i] * __ldg(w + i);
        #pragma unroll
        for (int o = 16; o > 0; o >>= 1)
            acc += __shfl_down_sync(0xFFFFFFFFu, acc, o);
        if (lane == 0)
            chown[s][tt] = acc + (s ? bc[j] : bu[j]);
    }
    __syncthreads();

    // ---- exact rank selection per stream ----
    #pragma unroll
    for (int s = 0; s < 2; s++) {
        if (tid < nc[s]) {
            const float v = chown[s][tid];
            const int   j = ci[s][tid];
            int r = 0;
            for (int t2 = 0; t2 < nc[s]; t2++) {
                const float o = chown[s][t2];
                r += (o > v) || (o == v && ci[s][t2] < j);
            }
            if (r < KHALF) {
                selidx[s][r] = j;
                selval[s][r] = v;
            }
        }
    }
    __syncthreads();
    if (tid == 0) cnt = KHALF;
    __syncthreads();

    // ---- build union; dups get both values free ----
    if (tid < KHALF) {
        const int j = selidx[0][tid];
        fidx[tid] = j;
        fhu [tid] = selval[0][tid];
        int miss = 0;                          // need hc by default
        #pragma unroll
        for (int q = 0; q < KHALF; q++) {
            if (selidx[1][q] == j) { fhc[tid] = selval[1][q]; miss = 2; }
        }
        fmiss[tid] = miss;
    }
    if (tid < KHALF) {
        const int j = selidx[1][tid];
        bool dup = false;
        #pragma unroll
        for (int q = 0; q < KHALF; q++) dup |= (selidx[0][q] == j);
        if (!dup) {
            int p = atomicAdd(&cnt, 1);
            fidx[p]  = j;
            fhc [p]  = selval[1][tid];
            fmiss[p] = 1;                      // need hu
        }
    }
    __syncthreads();

    // ---- phase B: cross dots only where missing ----
    const int fcnt = cnt;
    for (int e = wid; e < fcnt; e += 8) {
        const int miss = fmiss[e];
        if (miss == 2) continue;
        const int j = fidx[e];
        const float* w  = g_Wt[miss == 0 ? 1 : 0] + (size_t)j * INDIM;
        const float* xx = (miss == 0) ? sxc : sxu;
        float acc = 0.f;
        for (int i = lane; i < INDIM; i += 32)
            acc += xx[i] * __ldg(w + i);
        #pragma unroll
        for (int o = 16; o > 0; o >>= 1)
            acc += __shfl_down_sync(0xFFFFFFFFu, acc, o);
        if (lane == 0) {
            if (miss == 0) fhc[e] = acc + bc[j];
            else           fhu[e] = acc + bu[j];
        }
    }
    __syncthreads();

    // ---- write out + scatter ----
    if (tid < fcnt) {
        g_idx[row * MAXSEL + tid] = fidx[tid];
        g_hu [row * MAXSEL + tid] = fhu[tid];
        g_hc [row * MAXSEL + tid] = fhc[tid];
        const size_t o = (size_t)row * DICT + fidx[tid];
        mk[o] = 1.0f;
        zu[o] = fmaxf(fhu[tid], 0.f);
        zc[o] = fmaxf(fhc[tid], 0.f);
    }
    if (tid == 0) g_nsel[row] = fcnt;
}

// ---------------- decode (both decoders in one launch) ------------------------
__global__ void __launch_bounds__(256)
decode_kernel(const float* __restrict__ Wdu, const float* __restrict__ Wdc,
              float* __restrict__ xuh, float* __restrict__ xuc,
              float* __restrict__ xch, float* __restrict__ xcc)
{
    __shared__ int   sn;
    __shared__ int   sidx[MAXSEL];
    __shared__ float ca[MAXSEL], cb[MAXSEL];
    const int row    = blockIdx.x & (BATCH - 1);
    const int A_is_u = (blockIdx.x < BATCH);
    const int tid = threadIdx.x;

    const float* Wd   = A_is_u ? Wdu : Wdc;
    float* outA       = A_is_u ? xuh : xch;
    float* outB       = A_is_u ? xuc : xcc;

    if (tid == 0) sn = g_nsel[row];
    if (tid < MAXSEL) {
        sidx[tid] = g_idx[row * MAXSEL + tid];
        float zu = fmaxf(g_hu[row * MAXSEL + tid], 0.f);
        float zc = fmaxf(g_hc[row * MAXSEL + tid], 0.f);
        ca[tid] = A_is_u ? zu : zc;
        cb[tid] = A_is_u ? zc : zu;
    }
    __syncthreads();

    float4 a = make_float4(0.f, 0.f, 0.f, 0.f);
    float4 b = make_float4(0.f, 0.f, 0.f, 0.f);
    const int n = sn;
    #pragma unroll 4
    for (int s = 0; s < n; s++) {
        const float4 w = *reinterpret_cast<const float4*>(
            Wd + (size_t)sidx[s] * INDIM + tid * 4);
        const float fa = ca[s], fb = cb[s];
        a.x += fa * w.x; a.y += fa * w.y; a.z += fa * w.z; a.w += fa * w.w;
        b.x += fb * w.x; b.y += fb * w.y; b.z += fb * w.z; b.w += fb * w.w;
    }
    const size_t o = (size_t)row * INDIM + tid * 4;
    *reinterpret_cast<float4*>(outA + o) = a;
    *reinterpret_cast<float4*>(outB + o) = b;
}

// ---------------- launch ----------------------------------------------------
extern "C" void kernel_launch(void* const* d_in, const int* in_sizes, int n_in,
                              void* d_out, int out_size)
{
    const float* x_u     = (const float*)d_in[0];
    const float* x_c     = (const float*)d_in[1];
    const float* W_enc_u = (const float*)d_in[2];
    const float* b_enc_u = (const float*)d_in[3];
    const float* W_enc_c = (const float*)d_in[4];
    const float* b_enc_c = (const float*)d_in[5];
    const float* W_dec_u = (const float*)d_in[6];
    const float* W_dec_c = (const float*)d_in[7];

    float* out = (float*)d_out;
    const size_t ZN = (size_t)BATCH * DICT;
    const size_t XN = (size_t)BATCH * INDIM;
    float* z_u = out;
    float* z_c = out + ZN;
    float* mk  = out + 2 * ZN;
    float* xuh = out + 3 * ZN;
    float* xch = xuh + XN;
    float* xuc = xch + XN;
    float* xcc = xuc + XN;

    cudaFuncSetAttribute(gemm_bf16, cudaFuncAttributeMaxDynamicSharedMemorySize, GEMM_SMEM);

    conv_x<<<2048, 256>>>(x_u, x_c);
    trans_w<<<dim3(DICT / 32, INDIM / 32, 2), dim3(32, 8)>>>(W_enc_u, W_enc_c);

    dim3 ggrid(BATCH / GBM, DICT / GBN, 2);   // both encoders, one launch
    gemm_bf16<<<ggrid, GTHREADS, GEMM_SMEM>>>(b_enc_u, b_enc_c, z_u, z_c, mk);

    topcand<<<BATCH, 256>>>();

    rescore<<<BATCH, 256>>>(x_u, x_c, b_enc_u, b_enc_c, z_u, z_c, mk);

    decode_kernel<<<2 * BATCH, 256>>>(W_dec_u, W_dec_c, xuh, xuc, xch, xcc);
}

// round 14
// speedup vs baseline: 1.0502x; 1.0457x over previous
#include <cuda_runtime.h>
#include <cuda_bf16.h>
#include <cstdint>
#include <cstddef>

#define BATCH   4096
#define INDIM   1024
#define DICT    16384
#define KHALF   32
#define MAXSEL  64
#define CANDMAX 160
#define MARGIN  0.06f

// ---------------- __device__ scratch (no allocs) ----------------------------
__device__ __nv_bfloat16 g_xb [2][(size_t)BATCH * INDIM];
__device__ __nv_bfloat16 g_Wtb[2][(size_t)DICT * INDIM];   // W^T bf16 [N,K]
__device__ float         g_Wt [2][(size_t)DICT * INDIM];   // W^T fp32 [N,K]
__device__ __nv_bfloat16 g_hb [2][(size_t)BATCH * DICT];   // h~ bf16
__device__ int   g_cn [2][BATCH];
__device__ int   g_ci [2][BATCH][CANDMAX];
__device__ float g_chu[2][BATCH][CANDMAX];   // exact h_u per candidate
__device__ float g_chc[2][BATCH][CANDMAX];   // exact h_c per candidate
__device__ int   g_fcnt[DICT];
__device__ int   g_foff[DICT + 1];
__device__ int   g_fcur[DICT];
__device__ int   g_fent[2 * BATCH * CANDMAX];
__device__ int   g_nsel[BATCH];
__device__ int   g_idx [BATCH * MAXSEL];
__device__ float g_hu  [BATCH * MAXSEL];
__device__ float g_hc  [BATCH * MAXSEL];

// ---------------- PTX helpers (sm_80-era only) -------------------------------
__device__ __forceinline__ uint32_t smem_u32(const void* p) {
    uint32_t a;
    asm("{ .reg .u64 t; cvta.to.shared.u64 t, %1; cvt.u32.u64 %0, t; }" : "=r"(a) : "l"(p));
    return a;
}
__device__ __forceinline__ void cpa16(uint32_t s, const void* g) {
    asm volatile("cp.async.cg.shared.global [%0], [%1], 16;" :: "r"(s), "l"(g));
}
__device__ __forceinline__ void cpa_commit() { asm volatile("cp.async.commit_group;" ::: "memory"); }
__device__ __forceinline__ void cpa_wait3()  { asm volatile("cp.async.wait_group 3;" ::: "memory"); }

__device__ __forceinline__ void ldsm4(uint32_t* r, uint32_t addr) {
    asm volatile("ldmatrix.sync.aligned.m8n8.x4.shared.b16 {%0,%1,%2,%3}, [%4];"
        : "=r"(r[0]), "=r"(r[1]), "=r"(r[2]), "=r"(r[3]) : "r"(addr));
}
__device__ __forceinline__ void mma16816(float* d, const uint32_t* a, const uint32_t* b) {
    asm volatile("mma.sync.aligned.m16n8k16.row.col.f32.bf16.bf16.f32 "
        "{%0,%1,%2,%3}, {%4,%5,%6,%7}, {%8,%9}, {%0,%1,%2,%3};"
        : "+f"(d[0]), "+f"(d[1]), "+f"(d[2]), "+f"(d[3])
        : "r"(a[0]), "r"(a[1]), "r"(a[2]), "r"(a[3]), "r"(b[0]), "r"(b[1]));
}

// ---------------- preprocessing ---------------------------------------------
__global__ void conv_x(const float* __restrict__ xu, const float* __restrict__ xc)
{
    size_t n = (size_t)BATCH * INDIM;
    for (size_t i = (size_t)blockIdx.x * blockDim.x + threadIdx.x; i < n;
         i += (size_t)gridDim.x * blockDim.x) {
        g_xb[0][i] = __float2bfloat16_rn(xu[i]);
        g_xb[1][i] = __float2bfloat16_rn(xc[i]);
    }
}

__global__ void trans_w(const float* __restrict__ Wu, const float* __restrict__ Wc)
{
    __shared__ float t[32][33];
    const int enc = blockIdx.z;
    const float* W = enc ? Wc : Wu;
    const int n0 = blockIdx.x * 32, k0 = blockIdx.y * 32;
    const int tx = threadIdx.x, ty = threadIdx.y;
    #pragma unroll
    for (int j = 0; j < 4; j++)
        t[ty + j * 8][tx] = W[(size_t)(k0 + ty + j * 8) * DICT + n0 + tx];
    __syncthreads();
    #pragma unroll
    for (int j = 0; j < 4; j++) {
        float v = t[tx][ty + j * 8];
        size_t o = (size_t)(n0 + ty + j * 8) * INDIM + k0 + tx;
        g_Wt [enc][o] = v;
        g_Wtb[enc][o] = __float2bfloat16_rn(v);
    }
}

// -- bf16 mma.sync GEMM (R11 config, fused encoders) --------------------------
#define GBM 128
#define GBN 128
#define GBK 32
#define GROWB 40
#define GSTB  20480
#define GST   4
#define GEMM_SMEM (GST * GSTB)
#define NKI (INDIM / GBK)
#define GTHREADS 128

__device__ __forceinline__ void g_load(uint32_t sbase,
    const __nv_bfloat16* __restrict__ Xb, const __nv_bfloat16* __restrict__ Wb,
    int m0, int n0, int k0, int tid)
{
    #pragma unroll
    for (int r = 0; r < 4; r++) {
        int i = tid + r * GTHREADS;
        int row = i >> 2, c = i & 3;
        cpa16(sbase + row * 80 + c * 16,
              Xb + (size_t)(m0 + row) * INDIM + k0 + c * 8);
        cpa16(sbase + 10240 + row * 80 + c * 16,
              Wb + (size_t)(n0 + row) * INDIM + k0 + c * 8);
    }
}

__global__ void __launch_bounds__(GTHREADS, 2)
gemm_bf16(const float* __restrict__ bu, const float* __restrict__ bc,
          float* __restrict__ z_u, float* __restrict__ z_c, float* __restrict__ mk)
{
    extern __shared__ __align__(128) char sm[];
    __shared__ float s_bias[GBN];
    const uint32_t sb = smem_u32(sm);
    const int tid = threadIdx.x, lane = tid & 31, wid = tid >> 5;
    const int wm = wid & 1, wn = wid >> 1;
    const int enc = blockIdx.z;
    const int m0 = blockIdx.x * GBM;
    const int n0 = blockIdx.y * GBN;

    const float* bias = enc ? bc : bu;
    float* zfill = enc ? z_c : z_u;
    float* mfill = enc ? nullptr : mk;

    const __nv_bfloat16* Xb = g_xb [enc];
    const __nv_bfloat16* Wb = g_Wtb[enc];
    __nv_bfloat16* C = g_hb[enc];

    s_bias[tid] = bias[n0 + tid];

    const uint32_t aBase = ((wm * 64 + (lane & 15)) * GROWB + ((lane >> 4) << 3)) * 2;
    const uint32_t bBase = ((wn * 64 + (lane & 7) + ((lane >> 4) << 3)) * GROWB
                           + (((lane >> 3) & 1) << 3)) * 2;

    #pragma unroll
    for (int p = 0; p < GST; p++) {
        g_load(sb + p * GSTB, Xb, Wb, m0, n0, p * GBK, tid);
        cpa_commit();
    }

    float acc[4][8][4];
    #pragma unroll
    for (int a = 0; a < 4; a++)
        #pragma unroll
        for (int b = 0; b < 8; b++)
            #pragma unroll
            for (int c = 0; c < 4; c++) acc[a][b][c] = 0.f;

    for (int t = 0; t < NKI; t++) {
        const int s = t & (GST - 1);
        const uint32_t sA = sb + s * GSTB, sB = sA + 10240;

        cpa_wait3();
        __syncthreads();

        uint32_t af[2][4][4];
        uint32_t bf[2][4];

        #pragma unroll
        for (int mi = 0; mi < 4; mi++)
            ldsm4(af[0][mi], sA + aBase + (mi * 16 * GROWB) * 2);
        ldsm4(bf[0], sB + bBase);

        #pragma unroll
        for (int ks2 = 0; ks2 < 2; ks2++) {
            #pragma unroll
            for (int nh = 0; nh < 4; nh++) {
                const int cur = (ks2 * 4 + nh) & 1, nxt = cur ^ 1;
                if (nh < 3)
                    ldsm4(bf[nxt], sB + bBase + (ks2 * 16 + (nh + 1) * 16 * GROWB) * 2);
                else if (ks2 == 0)
                    ldsm4(bf[nxt], sB + bBase + 16 * 2);
                if (ks2 == 0 && nh == 2) {
                    ldsm4(af[1][0], sA + aBase + (16 + 0 * 16 * GROWB) * 2);
                    ldsm4(af[1][1], sA + aBase + (16 + 1 * 16 * GROWB) * 2);
                }
                if (ks2 == 0 && nh == 3) {
                    ldsm4(af[1][2], sA + aBase + (16 + 2 * 16 * GROWB) * 2);
                    ldsm4(af[1][3], sA + aBase + (16 + 3 * 16 * GROWB) * 2);
                }
                #pragma unroll
                for (int mi = 0; mi < 4; mi++) {
                    mma16816(acc[mi][nh * 2],     af[ks2][mi], bf[cur]);
                    mma16816(acc[mi][nh * 2 + 1], af[ks2][mi], bf[cur] + 2);
                }
            }
        }
        __syncthreads();

        if (t + GST < NKI)
            g_load(sb + s * GSTB, Xb, Wb, m0, n0, (t + GST) * GBK, tid);
        cpa_commit();
    }

    #pragma unroll
    for (int mi = 0; mi < 4; mi++) {
        const int rbase = m0 + wm * 64 + mi * 16 + (lane >> 2);
        #pragma unroll
        for (int ni = 0; ni < 8; ni++) {
            const int cl = wn * 64 + ni * 8 + (lane & 3) * 2;
            const float b0 = s_bias[cl], b1 = s_bias[cl + 1];
            __nv_bfloat162 v0 = __float22bfloat162_rn(
                make_float2(acc[mi][ni][0] + b0, acc[mi][ni][1] + b1));
            __nv_bfloat162 v1 = __float22bfloat162_rn(
                make_float2(acc[mi][ni][2] + b0, acc[mi][ni][3] + b1));
            *reinterpret_cast<__nv_bfloat162*>(C + (size_t)rbase * DICT + n0 + cl) = v0;
            *reinterpret_cast<__nv_bfloat162*>(C + (size_t)(rbase + 8) * DICT + n0 + cl) = v1;
        }
    }

    const float4 zz = make_float4(0.f, 0.f, 0.f, 0.f);
    #pragma unroll
    for (int i = tid; i < (GBM * GBN) / 4; i += GTHREADS) {
        const int r = i >> 5, c = i & 31;
        *reinterpret_cast<float4*>(zfill + (size_t)(m0 + r) * DICT + n0 + c * 4) = zz;
    }
    if (mfill) {
        #pragma unroll
        for (int i = tid; i < (GBM * GBN) / 4; i += GTHREADS) {
            const int r = i >> 5, c = i & 31;
            *reinterpret_cast<float4*>(mfill + (size_t)(m0 + r) * DICT + n0 + c * 4) = zz;
        }
    }
}

// ---------------- candidate selection (register-resident) --------------------
__global__ void __launch_bounds__(256)
topcand()
{
    __shared__ int wcnt[8];
    __shared__ int s_cnt;
    const int row = blockIdx.x, tid = threadIdx.x;
    const int lane = tid & 31, wid = tid >> 5;

    for (int stream = 0; stream < 2; stream++) {
        const __nv_bfloat16* src = g_hb[stream] + (size_t)row * DICT;
        uint4 d[8];
        #pragma unroll
        for (int j = 0; j < 8; j++)
            d[j] = reinterpret_cast<const uint4*>(src)[tid + j * 256];

        unsigned lo = 0, hi = 0xFFFFu;
        #pragma unroll 1
        while (lo < hi) {
            const unsigned mid = (lo + hi + 1) >> 1;
            const unsigned short tb = (mid & 0x8000u)
                ? (unsigned short)(mid & 0x7FFFu)
                : (unsigned short)(~mid & 0xFFFFu);
            __nv_bfloat16_raw rr; rr.x = tb;
            const __nv_bfloat16 t1 = __nv_bfloat16(rr);
            const __nv_bfloat162 tv = __nv_bfloat162(t1, t1);

            __nv_bfloat162 accp = __nv_bfloat162(__float2bfloat16(0.f), __float2bfloat16(0.f));
            #pragma unroll
            for (int j = 0; j < 8; j++) {
                const __nv_bfloat162* p = reinterpret_cast<const __nv_bfloat162*>(&d[j]);
                #pragma unroll
                for (int q = 0; q < 4; q++)
                    accp = __hadd2(accp, __hge2(p[q], tv));
            }
            int c = (int)(__low2float(accp) + __high2float(accp));
            #pragma unroll
            for (int o = 16; o > 0; o >>= 1)
                c += __shfl_down_sync(0xFFFFFFFFu, c, o);
            if (lane == 0) wcnt[wid] = c;
            __syncthreads();
            if (tid == 0) {
                int tot = 0;
                #pragma unroll
                for (int w = 0; w < 8; w++) tot += wcnt[w];
                s_cnt = tot;
            }
            __syncthreads();
            if (s_cnt >= KHALF) lo = mid; else hi = mid - 1;
            __syncthreads();
        }

        const unsigned short vb = (lo & 0x8000u)
            ? (unsigned short)(lo & 0x7FFFu)
            : (unsigned short)(~lo & 0xFFFFu);
        __nv_bfloat16_raw vr; vr.x = vb;
        const float cut = __bfloat162float(__nv_bfloat16(vr)) - MARGIN;

        if (tid == 0) s_cnt = 0;
        __syncthreads();
        #pragma unroll
        for (int j = 0; j < 8; j++) {
            const __nv_bfloat16* p = reinterpret_cast<const __nv_bfloat16*>(&d[j]);
            #pragma unroll
            for (int q = 0; q < 8; q++) {
                if (__bfloat162float(p[q]) > cut) {
                    int pos = atomicAdd(&s_cnt, 1);
                    if (pos < CANDMAX)
                        g_ci[stream][row][pos] = (tid + j * 256) * 8 + q;
                }
            }
        }
        __syncthreads();
        if (tid == 0) g_cn[stream][row] = s_cnt < CANDMAX ? s_cnt : CANDMAX;
        __syncthreads();
    }
}

// ---------------- CSR build: feature -> candidate entries --------------------
__global__ void zero_fcnt()
{
    int i = blockIdx.x * blockDim.x + threadIdx.x;
    if (i < DICT) g_fcnt[i] = 0;
}

__global__ void __launch_bounds__(256)
cand_count()
{
    const int row = blockIdx.x, tid = threadIdx.x;
    #pragma unroll
    for (int s = 0; s < 2; s++)
        if (tid < g_cn[s][row])
            atomicAdd(&g_fcnt[g_ci[s][row][tid]], 1);
}

__global__ void __launch_bounds__(1024)
scan_kernel()
{
    __shared__ int part[1024];
    const int tid = threadIdx.x;
    const int base = tid * 16;
    int local[16];
    int sum = 0;
    #pragma unroll
    for (int k = 0; k < 16; k++) { local[k] = g_fcnt[base + k]; sum += local[k]; }
    part[tid] = sum;
    __syncthreads();
    for (int off = 1; off < 1024; off <<= 1) {
        int v = (tid >= off) ? part[tid - off] : 0;
        __syncthreads();
        part[tid] += v;
        __syncthreads();
    }
    int run = (tid > 0) ? part[tid - 1] : 0;
    #pragma unroll
    for (int k = 0; k < 16; k++) {
        g_foff[base + k] = run;
        g_fcur[base + k] = run;
        run += local[k];
    }
    if (tid == 1023) g_foff[DICT] = run;
}

__global__ void __launch_bounds__(256)
cand_fill()
{
    const int row = blockIdx.x, tid = threadIdx.x;
    #pragma unroll
    for (int s = 0; s < 2; s++)
        if (tid < g_cn[s][row]) {
            const int j = g_ci[s][row][tid];
            const int pos = atomicAdd(&g_fcur[j], 1);
            g_fent[pos] = row | (s << 12) | (tid << 13);
        }
}

// feature-major exact dots: one block per feature, streams W sequentially
__global__ void __launch_bounds__(256)
cand_dot(const float* __restrict__ xu, const float* __restrict__ xc,
         const float* __restrict__ bu, const float* __restrict__ bc)
{
    __shared__ float swu[INDIM], swc[INDIM];
    const int j = blockIdx.x;
    const int beg = g_foff[j], end = g_foff[j + 1];
    if (beg == end) return;
    const int tid = threadIdx.x, lane = tid & 31, wid = tid >> 5;

    const float* wu = g_Wt[0] + (size_t)j * INDIM;
    const float* wc = g_Wt[1] + (size_t)j * INDIM;
    #pragma unroll
    for (int k = 0; k < 4; k++) {
        swu[tid + k * 256] = wu[tid + k * 256];
        swc[tid + k * 256] = wc[tid + k * 256];
    }
    __syncthreads();
    const float bju = bu[j], bjc = bc[j];

    for (int e = beg + wid; e < end; e += 8) {
        const int ent  = g_fent[e];
        const int row  = ent & 4095;
        const int s    = (ent >> 12) & 1;
        const int slot = ent >> 13;
        const float* xur = xu + (size_t)row * INDIM;
        const float* xcr = xc + (size_t)row * INDIM;
        float du = 0.f, dc = 0.f;
        for (int i = lane; i < INDIM; i += 32) {
            du += xur[i] * swu[i];
            dc += xcr[i] * swc[i];
        }
        #pragma unroll
        for (int o = 16; o > 0; o >>= 1) {
            du += __shfl_down_sync(0xFFFFFFFFu, du, o);
            dc += __shfl_down_sync(0xFFFFFFFFu, dc, o);
        }
        if (lane == 0) {
            g_chu[s][row][slot] = du + bju;
            g_chc[s][row][slot] = dc + bjc;
        }
    }
}

// -------- selection + union + scatter (values precomputed) --------------------
__global__ void __launch_bounds__(256)
select_scatter(float* __restrict__ zu, float* __restrict__ zc, float* __restrict__ mk)
{
    __shared__ int   ci[2][CANDMAX];
    __shared__ float chu[2][CANDMAX], chc[2][CANDMAX];
    __shared__ int   nc[2];
    __shared__ int   selidx[2][KHALF];
    __shared__ float selhu[2][KHALF], selhc[2][KHALF];
    __shared__ int   cnt;

    const int row = blockIdx.x, tid = threadIdx.x;

    if (tid < 2) nc[tid] = g_cn[tid][row];
    __syncthreads();
    for (int s = 0; s < 2; s++)
        for (int t = tid; t < nc[s]; t += 256) {
            ci [s][t] = g_ci [s][row][t];
            chu[s][t] = g_chu[s][row][t];
            chc[s][t] = g_chc[s][row][t];
        }
    __syncthreads();

    #pragma unroll
    for (int s = 0; s < 2; s++) {
        if (tid < nc[s]) {
            const float v = s ? chc[1][tid] : chu[0][tid];
            const int   j = ci[s][tid];
            int r = 0;
            for (int t2 = 0; t2 < nc[s]; t2++) {
                const float o = s ? chc[1][t2] : chu[0][t2];
                r += (o > v) || (o == v && ci[s][t2] < j);
            }
            if (r < KHALF) {
                selidx[s][r] = j;
                selhu[s][r]  = chu[s][tid];
                selhc[s][r]  = chc[s][tid];
            }
        }
    }
    __syncthreads();
    if (tid == 0) cnt = KHALF;
    __syncthreads();

    if (tid < KHALF) {
        g_idx[row * MAXSEL + tid] = selidx[0][tid];
        g_hu [row * MAXSEL + tid] = selhu[0][tid];
        g_hc [row * MAXSEL + tid] = selhc[0][tid];
        const size_t o = (size_t)row * DICT + selidx[0][tid];
        mk[o] = 1.0f;
        zu[o] = fmaxf(selhu[0][tid], 0.f);
        zc[o] = fmaxf(selhc[0][tid], 0.f);
    }
    if (tid < KHALF) {
        const int j = selidx[1][tid];
        bool dup = false;
        #pragma unroll
        for (int q = 0; q < KHALF; q++) dup |= (selidx[0][q] == j);
        if (!dup) {
            int p = atomicAdd(&cnt, 1);
            g_idx[row * MAXSEL + p] = j;
            g_hu [row * MAXSEL + p] = selhu[1][tid];
            g_hc [row * MAXSEL + p] = selhc[1][tid];
            const size_t o = (size_t)row * DICT + j;
            mk[o] = 1.0f;
            zu[o] = fmaxf(selhu[1][tid], 0.f);
            zc[o] = fmaxf(selhc[1][tid], 0.f);
        }
    }
    __syncthreads();
    if (tid == 0) g_nsel[row] = cnt;
}

// ---------------- decode (both decoders in one launch) ------------------------
__global__ void __launch_bounds__(256)
decode_kernel(const float* __restrict__ Wdu, const float* __restrict__ Wdc,
              float* __restrict__ xuh, float* __restrict__ xuc,
              float* __restrict__ xch, float* __restrict__ xcc)
{
    __shared__ int   sn;
    __shared__ int   sidx[MAXSEL];
    __shared__ float ca[MAXSEL], cb[MAXSEL];
    const int row    = blockIdx.x & (BATCH - 1);
    const int A_is_u = (blockIdx.x < BATCH);
    const int tid = threadIdx.x;

    const float* Wd   = A_is_u ? Wdu : Wdc;
    float* outA       = A_is_u ? xuh : xch;
    float* outB       = A_is_u ? xuc : xcc;

    if (tid == 0) sn = g_nsel[row];
    if (tid < MAXSEL) {
        sidx[tid] = g_idx[row * MAXSEL + tid];
        float zu = fmaxf(g_hu[row * MAXSEL + tid], 0.f);
        float zc = fmaxf(g_hc[row * MAXSEL + tid], 0.f);
        ca[tid] = A_is_u ? zu : zc;
        cb[tid] = A_is_u ? zc : zu;
    }
    __syncthreads();

    float4 a = make_float4(0.f, 0.f, 0.f, 0.f);
    float4 b = make_float4(0.f, 0.f, 0.f, 0.f);
    const int n = sn;
    #pragma unroll 4
    for (int s = 0; s < n; s++) {
        const float4 w = *reinterpret_cast<const float4*>(
            Wd + (size_t)sidx[s] * INDIM + tid * 4);
        const float fa = ca[s], fb = cb[s];
        a.x += fa * w.x; a.y += fa * w.y; a.z += fa * w.z; a.w += fa * w.w;
        b.x += fb * w.x; b.y += fb * w.y; b.z += fb * w.z; b.w += fb * w.w;
    }
    const size_t o = (size_t)row * INDIM + tid * 4;
    *reinterpret_cast<float4*>(outA + o) = a;
    *reinterpret_cast<float4*>(outB + o) = b;
}

// ---------------- launch ----------------------------------------------------
extern "C" void kernel_launch(void* const* d_in, const int* in_sizes, int n_in,
                              void* d_out, int out_size)
{
    const float* x_u     = (const float*)d_in[0];
    const float* x_c     = (const float*)d_in[1];
    const float* W_enc_u = (const float*)d_in[2];
    const float* b_enc_u = (const float*)d_in[3];
    const float* W_enc_c = (const float*)d_in[4];
    const float* b_enc_c = (const float*)d_in[5];
    const float* W_dec_u = (const float*)d_in[6];
    const float* W_dec_c = (const float*)d_in[7];

    float* out = (float*)d_out;
    const size_t ZN = (size_t)BATCH * DICT;
    const size_t XN = (size_t)BATCH * INDIM;
    float* z_u = out;
    float* z_c = out + ZN;
    float* mk  = out + 2 * ZN;
    float* xuh = out + 3 * ZN;
    float* xch = xuh + XN;
    float* xuc = xch + XN;
    float* xcc = xuc + XN;

    cudaFuncSetAttribute(gemm_bf16, cudaFuncAttributeMaxDynamicSharedMemorySize, GEMM_SMEM);

    conv_x<<<2048, 256>>>(x_u, x_c);
    trans_w<<<dim3(DICT / 32, INDIM / 32, 2), dim3(32, 8)>>>(W_enc_u, W_enc_c);

    dim3 ggrid(BATCH / GBM, DICT / GBN, 2);
    gemm_bf16<<<ggrid, GTHREADS, GEMM_SMEM>>>(b_enc_u, b_enc_c, z_u, z_c, mk);

    topcand<<<BATCH, 256>>>();

    zero_fcnt<<<DICT / 256, 256>>>();
    cand_count<<<BATCH, 256>>>();
    scan_kernel<<<1, 1024>>>();
    cand_fill<<<BATCH, 256>>>();
    cand_dot<<<DICT, 256>>>(x_u, x_c, b_enc_u, b_enc_c);

    select_scatter<<<BATCH, 256>>>(z_u, z_c, mk);

    decode_kernel<<<2 * BATCH, 256>>>(W_dec_u, W_dec_c, xuh, xuc, xch, xcc);
}